// round 2
// baseline (speedup 1.0000x reference)
#include <cuda_runtime.h>
#include <cuda_bf16.h>
#include <mma.h>
#include <math.h>

using namespace nvcuda;

// Problem dims
#define T_  64
#define B_  64
#define S_  128
#define E_  512
#define H_  1024
#define EH_ 1536            // E + H
#define BH_ (B_*H_)         // 65536
#define TBH_ ((size_t)T_*B_*H_)
#define TBS_ ((size_t)T_*B_*S_)

// ---------------- scratch (device globals; allocation-free) ----------------
__device__ __align__(16) float g_ctxp[(size_t)B_*S_*H_];  // projected context (B,S,H)
__device__ __align__(16) float g_hb0[2*BH_];              // layer0 h ping-pong
__device__ __align__(16) float g_hb1[2*BH_];              // layer1 h ping-pong
__device__ __align__(16) float g_cb0[BH_];                // layer0 c (in-place)
__device__ __align__(16) float g_cb1[BH_];                // layer1 c (in-place)
__device__ __align__(16) float g_cvec[BH_];               // attention context vector
__device__ __align__(16) float g_zeros[BH_];              // never written -> stays 0

// ---------------- helpers ----------------
__device__ __forceinline__ float sigf(float x) { return 1.f / (1.f + expf(-x)); }

using FragA = wmma::fragment<wmma::matrix_a, 16, 16, 8, wmma::precision::tf32, wmma::row_major>;
using FragBc = wmma::fragment<wmma::matrix_b, 16, 16, 8, wmma::precision::tf32, wmma::col_major>;
using FragBr = wmma::fragment<wmma::matrix_b, 16, 16, 8, wmma::precision::tf32, wmma::row_major>;
using FragC = wmma::fragment<wmma::accumulator, 16, 16, 8, float>;

// One warp accumulates a 16x16 tile: C += A(16,K) * W(16,K)^T  (both K-major)
// A pre-offset to this warp's 16 rows; Wb pre-offset to this warp's 16 output
// columns' weight rows (col-major view, ld = ldw).
__device__ __forceinline__ void gemm_seg_tn(FragC& acc, const float* __restrict__ A, int lda,
                                            const float* __restrict__ Wb, int ldw, int Klen) {
    FragA af; FragBc bf;
    for (int k = 0; k < Klen; k += 8) {
        wmma::load_matrix_sync(af, A + k, lda);
        wmma::load_matrix_sync(bf, Wb + k, ldw);
#pragma unroll
        for (int i = 0; i < af.num_elements; i++) af.x[i] = wmma::__float_to_tf32(af.x[i]);
#pragma unroll
        for (int i = 0; i < bf.num_elements; i++) bf.x[i] = wmma::__float_to_tf32(bf.x[i]);
        wmma::mma_sync(acc, af, bf, acc);
    }
}

// ---------------- K0: ctx_p[b,s,d] = sum_k context[s,b,k] * W_a[k,d] ----------------
// grid (H/64, S/64, B), 128 threads (4 warps, each 64(s) x 16(d))
__global__ __launch_bounds__(128) void ctxp_kernel(const float* __restrict__ ctx,
                                                   const float* __restrict__ Wa) {
    int w = threadIdx.x >> 5;
    int d0 = blockIdx.x * 64 + w * 16;
    int s0 = blockIdx.y * 64;
    int b  = blockIdx.z;

    FragC acc[4];
#pragma unroll
    for (int i = 0; i < 4; i++) wmma::fill_fragment(acc[i], 0.f);

    FragA af; FragBr bf;
    for (int k = 0; k < H_; k += 8) {
        wmma::load_matrix_sync(bf, Wa + (size_t)k * H_ + d0, H_);
#pragma unroll
        for (int i = 0; i < bf.num_elements; i++) bf.x[i] = wmma::__float_to_tf32(bf.x[i]);
#pragma unroll
        for (int fi = 0; fi < 4; fi++) {
            const float* ap = ctx + ((size_t)(s0 + fi * 16) * B_ + b) * H_ + k;
            wmma::load_matrix_sync(af, ap, B_ * H_);
#pragma unroll
            for (int i = 0; i < af.num_elements; i++) af.x[i] = wmma::__float_to_tf32(af.x[i]);
            wmma::mma_sync(acc[fi], af, bf, acc[fi]);
        }
    }
#pragma unroll
    for (int fi = 0; fi < 4; fi++) {
        float* op = g_ctxp + ((size_t)b * S_ + s0 + fi * 16) * H_ + d0;
        wmma::store_matrix_sync(op, acc[fi], H_, wmma::mem_row_major);
    }
}

// ---------------- LSTM layer kernel (3 K-segments, fused cell) ----------------
// grid 64 (each CTA: 16 hidden cols x 4 gates), 512 threads (warp = (gate, m-quarter))
__global__ __launch_bounds__(512) void lstm_kernel(
    const float* __restrict__ A0, int lda0, const float* __restrict__ W0, int ldw0, int K0,
    const float* __restrict__ A1, int lda1, const float* __restrict__ W1, int ldw1, int K1,
    const float* __restrict__ A2, int lda2, const float* __restrict__ W2, int ldw2, int K2,
    const float* __restrict__ bi, const float* __restrict__ bh,
    const float* __restrict__ cprev, float* __restrict__ cout, float* __restrict__ hout) {
    __shared__ float gs[4][64][16];

    int w  = threadIdx.x >> 5;
    int g  = w >> 2;        // gate 0..3
    int mi = w & 3;         // m-quarter
    int j0 = blockIdx.x * 16;
    int nrow = g * H_ + j0; // weight row (output col) base for this warp

    FragC acc; wmma::fill_fragment(acc, 0.f);

    gemm_seg_tn(acc, A0 + (size_t)mi * 16 * lda0, lda0, W0 + (size_t)nrow * ldw0, ldw0, K0);
    gemm_seg_tn(acc, A1 + (size_t)mi * 16 * lda1, lda1, W1 + (size_t)nrow * ldw1, ldw1, K1);
    if (K2 > 0)
        gemm_seg_tn(acc, A2 + (size_t)mi * 16 * lda2, lda2, W2 + (size_t)nrow * ldw2, ldw2, K2);

    wmma::store_matrix_sync(&gs[g][mi * 16][0], acc, 16, wmma::mem_row_major);
    __syncthreads();

    for (int e = threadIdx.x; e < 64 * 16; e += 512) {
        int m = e >> 4, j = e & 15;
        int n = j0 + j;
        float iv = gs[0][m][j] + bi[n]          + bh[n];
        float fv = gs[1][m][j] + bi[H_ + n]     + bh[H_ + n];
        float gv = gs[2][m][j] + bi[2 * H_ + n] + bh[2 * H_ + n];
        float ov = gs[3][m][j] + bi[3 * H_ + n] + bh[3 * H_ + n];
        float cp = cprev[(size_t)m * H_ + n];
        float c2 = sigf(fv) * cp + sigf(iv) * tanhf(gv);
        float h2 = sigf(ov) * tanhf(c2);
        cout[(size_t)m * H_ + n] = c2;
        hout[(size_t)m * H_ + n] = h2;
    }
}

// ---------------- attention kernel: scores -> softmax -> cvec ----------------
// grid B_, 512 threads
__global__ __launch_bounds__(512) void attn_kernel(const float* __restrict__ h1,
                                                   const float* __restrict__ ctx,
                                                   float* __restrict__ attns_t) {
    __shared__ __align__(16) float h1s[H_];
    __shared__ float sc[S_];
    __shared__ float salign[S_];
    __shared__ float red[8];

    int b = blockIdx.x, tid = threadIdx.x;
    int w = tid >> 5, l = tid & 31;

    for (int i = tid; i < H_; i += 512) h1s[i] = h1[(size_t)b * H_ + i];
    __syncthreads();

    // scores: warp w handles s = w*8 .. w*8+7
    const float4* h14 = (const float4*)h1s;
    float accv[8];
#pragma unroll
    for (int i = 0; i < 8; i++) accv[i] = 0.f;
#pragma unroll
    for (int j = 0; j < 8; j++) {
        float4 hv = h14[j * 32 + l];
#pragma unroll
        for (int i = 0; i < 8; i++) {
            const float4* row = (const float4*)(g_ctxp + ((size_t)b * S_ + w * 8 + i) * H_);
            float4 c = row[j * 32 + l];
            accv[i] += hv.x * c.x + hv.y * c.y + hv.z * c.z + hv.w * c.w;
        }
    }
#pragma unroll
    for (int i = 0; i < 8; i++) {
        float v = accv[i];
#pragma unroll
        for (int o = 16; o > 0; o >>= 1) v += __shfl_xor_sync(0xFFFFFFFFu, v, o);
        if (l == 0) sc[w * 8 + i] = v;
    }
    __syncthreads();

    // softmax over 128 scores (first 4 warps)
    float mx = -3.4e38f;
    if (tid < 128) mx = sc[tid];
#pragma unroll
    for (int o = 16; o > 0; o >>= 1) mx = fmaxf(mx, __shfl_xor_sync(0xFFFFFFFFu, mx, o));
    if (tid < 128 && l == 0) red[w] = mx;
    __syncthreads();
    float gmx = fmaxf(fmaxf(red[0], red[1]), fmaxf(red[2], red[3]));
    float e = 0.f;
    if (tid < 128) { e = expf(sc[tid] - gmx); salign[tid] = e; }
    float se = e;
#pragma unroll
    for (int o = 16; o > 0; o >>= 1) se += __shfl_xor_sync(0xFFFFFFFFu, se, o);
    if (tid < 128 && l == 0) red[4 + w] = se;
    __syncthreads();
    float inv = 1.f / (red[4] + red[5] + red[6] + red[7]);
    if (tid < 128) {
        float a = salign[tid] * inv;
        salign[tid] = a;
        attns_t[(size_t)b * S_ + tid] = a;
    }
    __syncthreads();

    // cvec[d] = sum_s align[s] * ctx[s,b,d]; thread -> d pair (2*tid, 2*tid+1)
    float2 accc = make_float2(0.f, 0.f);
#pragma unroll 8
    for (int s = 0; s < S_; s++) {
        float a = salign[s];
        float2 c = *(const float2*)(ctx + ((size_t)s * B_ + b) * H_ + tid * 2);
        accc.x += a * c.x;
        accc.y += a * c.y;
    }
    g_cvec[(size_t)b * H_ + tid * 2]     = accc.x;
    g_cvec[(size_t)b * H_ + tid * 2 + 1] = accc.y;
}

// ---------------- output projection: attn_h = tanh([cvec, h1] @ W_out^T) ----------------
// grid H/64, 512 threads (warp = (n-16-group, m-quarter))
__global__ __launch_bounds__(512) void outproj_kernel(const float* __restrict__ h1,
                                                      const float* __restrict__ Wout,
                                                      float* __restrict__ outs_t) {
    int w = threadIdx.x >> 5;
    int nj = w >> 2, mi = w & 3;
    int col = blockIdx.x * 64 + nj * 16;

    FragC acc; wmma::fill_fragment(acc, 0.f);
    gemm_seg_tn(acc, g_cvec + (size_t)mi * 16 * H_, H_, Wout + (size_t)col * (2 * H_), 2 * H_, H_);
    gemm_seg_tn(acc, h1 + (size_t)mi * 16 * H_, H_, Wout + (size_t)col * (2 * H_) + H_, 2 * H_, H_);
#pragma unroll
    for (int i = 0; i < acc.num_elements; i++) acc.x[i] = tanhf(acc.x[i]);
    wmma::store_matrix_sync(outs_t + (size_t)mi * 16 * H_ + col, acc, H_, wmma::mem_row_major);
}

// ---------------- finalize: copy states into d_out ----------------
__global__ __launch_bounds__(256) void finalize_kernel(float* __restrict__ hF, float* __restrict__ cF) {
    int i = blockIdx.x * blockDim.x + threadIdx.x;
    if (i < BH_) {
        hF[i]        = g_hb0[i];
        hF[BH_ + i]  = g_hb1[i];
        cF[i]        = g_cb0[i];
        cF[BH_ + i]  = g_cb1[i];
    }
}

// ---------------- host launcher ----------------
extern "C" void kernel_launch(void* const* d_in, const int* in_sizes, int n_in,
                              void* d_out, int out_size) {
    const float* inp    = (const float*)d_in[0];
    const float* ctx    = (const float*)d_in[1];
    const float* h0in   = (const float*)d_in[2];
    const float* c0in   = (const float*)d_in[3];
    const float* W_ih0  = (const float*)d_in[4];
    const float* b_ih0  = (const float*)d_in[5];
    const float* W_hh0  = (const float*)d_in[6];
    const float* b_hh0  = (const float*)d_in[7];
    const float* W_ih1  = (const float*)d_in[8];
    const float* b_ih1  = (const float*)d_in[9];
    const float* W_hh1  = (const float*)d_in[10];
    const float* b_hh1  = (const float*)d_in[11];
    const float* W_a    = (const float*)d_in[12];
    const float* W_out  = (const float*)d_in[13];

    float* out   = (float*)d_out;
    float* outs  = out;                          // (T,B,H)
    float* hF    = out + TBH_;                   // (2,B,H)
    float* cF    = hF + 2 * BH_;                 // (2,B,H)
    float* attns = cF + 2 * BH_;                 // (T,B,S)

    float *hb0, *hb1, *cb0, *cb1, *zeros;
    cudaGetSymbolAddress((void**)&hb0, g_hb0);
    cudaGetSymbolAddress((void**)&hb1, g_hb1);
    cudaGetSymbolAddress((void**)&cb0, g_cb0);
    cudaGetSymbolAddress((void**)&cb1, g_cb1);
    cudaGetSymbolAddress((void**)&zeros, g_zeros);

    // Precompute projected context
    dim3 g0(H_ / 64, S_ / 64, B_);
    ctxp_kernel<<<g0, 128>>>(ctx, W_a);

    for (int t = 0; t < T_; t++) {
        const float* feed = t ? outs + (size_t)(t - 1) * B_ * H_ : zeros;
        const float* h0p  = t ? hb0 + (size_t)(t & 1) * BH_ : h0in;
        const float* h1p  = t ? hb1 + (size_t)(t & 1) * BH_ : h0in + BH_;
        const float* c0p  = t ? cb0 : c0in;
        const float* c1p  = t ? cb1 : c0in + BH_;
        float* h0n = hb0 + (size_t)((t + 1) & 1) * BH_;
        float* h1n = hb1 + (size_t)((t + 1) & 1) * BH_;

        // layer 0: gates = [emb, feed] @ W_ih0^T + h0 @ W_hh0^T
        lstm_kernel<<<64, 512>>>(
            inp + (size_t)t * B_ * E_, E_, W_ih0,       EH_, E_,
            feed,                      H_, W_ih0 + E_,  EH_, H_,
            h0p,                       H_, W_hh0,       H_,  H_,
            b_ih0, b_hh0, c0p, cb0, h0n);

        // layer 1: gates = h0n @ W_ih1^T + h1 @ W_hh1^T
        lstm_kernel<<<64, 512>>>(
            h0n, H_, W_ih1, H_, H_,
            h1p, H_, W_hh1, H_, H_,
            h0n, H_, W_hh1, H_, 0,    // unused third segment
            b_ih1, b_hh1, c1p, cb1, h1n);

        // attention
        attn_kernel<<<B_, 512>>>(h1n, ctx, attns + (size_t)t * B_ * S_);

        // output projection (also the input-feed for step t+1, read from outs[t])
        outproj_kernel<<<H_ / 64, 512>>>(h1n, W_out, outs + (size_t)t * B_ * H_);
    }

    finalize_kernel<<<(BH_ + 255) / 256, 256>>>(hF, cF);
}

// round 4
// speedup vs baseline: 1.8762x; 1.8762x over previous
#include <cuda_runtime.h>
#include <cuda_bf16.h>
#include <mma.h>
#include <math.h>

using namespace nvcuda;

#define T_  64
#define B_  64
#define S_  128
#define E_  512
#define H_  1024
#define EH_ 1536
#define BH_ (B_*H_)
#define TBH_ ((size_t)T_*B_*H_)

// ---------------- scratch ----------------
__device__ __align__(16) float g_ctxp[(size_t)B_*S_*H_];
__device__ __align__(16) float g_hb0[2*BH_];
__device__ __align__(16) float g_hb1[2*BH_];
__device__ __align__(16) float g_cb0[BH_];
__device__ __align__(16) float g_cb1[BH_];
__device__ __align__(16) float g_cvec[BH_];
__device__ __align__(16) float g_scores[B_*S_];
__device__ __align__(16) float g_zeros[BH_];  // never written -> stays 0

__device__ __forceinline__ float sigf(float x) { return 1.f / (1.f + expf(-x)); }

__device__ __forceinline__ void cp16(float* dst, const float* src) {
    unsigned s = (unsigned)__cvta_generic_to_shared(dst);
    asm volatile("cp.async.cg.shared.global [%0], [%1], 16;\n" :: "r"(s), "l"(src));
}
__device__ __forceinline__ void cp_commit() { asm volatile("cp.async.commit_group;\n"); }

using FragA = wmma::fragment<wmma::matrix_a, 16, 16, 8, wmma::precision::tf32, wmma::row_major>;
using FragB = wmma::fragment<wmma::matrix_b, 16, 16, 8, wmma::precision::tf32, wmma::col_major>;
using FragBr = wmma::fragment<wmma::matrix_b, 16, 16, 8, wmma::precision::tf32, wmma::row_major>;
using FragC = wmma::fragment<wmma::accumulator, 16, 16, 8, float>;

// ============ main GEMM: C(64 x 64cols) = sum_seg A_seg(64,K)@W_seg(cols,K)^T ============
// gateMode=1: cols = {g*H + n0 + j}, LSTM cell epilogue.
// gateMode=0: cols = n0..n0+63 contiguous, tanh epilogue, write to hout (ld=H).
__global__ __launch_bounds__(256) void gemm_kernel(
    const float* __restrict__ A0, int lda0, const float* __restrict__ W0, int ldw0, int kt0,
    const float* __restrict__ A1, int lda1, const float* __restrict__ W1, int ldw1, int kt1,
    const float* __restrict__ A2, int lda2, const float* __restrict__ W2, int ldw2, int kt2,
    int gateMode,
    const float* __restrict__ bi, const float* __restrict__ bh,
    const float* __restrict__ cprev, float* __restrict__ cout, float* __restrict__ hout) {

    __shared__ __align__(16) float sA[2][64 * 40];
    __shared__ __align__(16) float sW[2][64 * 40];

    const int tid = threadIdx.x;
    const int w = tid >> 5;
    const int wm = w >> 2, wn = w & 3;
    const int n0 = blockIdx.x * (gateMode ? 16 : 64);

    // per-thread copy coords: 2 float4 chunks for A, 2 for W
    const int q0 = tid * 2, q1 = q0 + 1;
    const int r0 = q0 >> 3, c0 = (q0 & 7) * 4;
    const int r1 = q1 >> 3, c1 = (q1 & 7) * 4;
    const int wr0 = gateMode ? ((r0 >> 4) * H_ + n0 + (r0 & 15)) : (n0 + r0);
    const int wr1 = gateMode ? ((r1 >> 4) * H_ + n0 + (r1 & 15)) : (n0 + r1);

    const float* segA[3] = {A0, A1, A2}; int slda[3] = {lda0, lda1, lda2};
    const float* segW[3] = {W0, W1, W2}; int sldw[3] = {ldw0, ldw1, ldw2};
    int skt[3] = {kt0, kt1, kt2};
    const int tot = kt0 + kt1 + kt2;

    int is = 0, ik = 0;
    auto issue = [&](int buf) {
        const float* Ab = segA[is]; int la = slda[is];
        const float* Wb = segW[is]; int lw = sldw[is];
        int ko = ik * 32;
        cp16(&sA[buf][r0 * 40 + c0], Ab + (size_t)r0 * la + ko + c0);
        cp16(&sA[buf][r1 * 40 + c1], Ab + (size_t)r1 * la + ko + c1);
        cp16(&sW[buf][r0 * 40 + c0], Wb + (size_t)wr0 * lw + ko + c0);
        cp16(&sW[buf][r1 * 40 + c1], Wb + (size_t)wr1 * lw + ko + c1);
        cp_commit();
        if (++ik == skt[is]) { ik = 0; ++is; }
    };

    FragC acc0, acc1;
    wmma::fill_fragment(acc0, 0.f);
    wmma::fill_fragment(acc1, 0.f);

    issue(0);
    for (int it = 0; it < tot; ++it) {
        const int buf = it & 1;
        if (it + 1 < tot) { issue((it + 1) & 1); asm volatile("cp.async.wait_group 1;\n"); }
        else              {                      asm volatile("cp.async.wait_group 0;\n"); }
        __syncthreads();

        const float* pA = &sA[buf][wm * 32 * 40];
        const float* pB = &sW[buf][wn * 16 * 40];
#pragma unroll
        for (int kk = 0; kk < 32; kk += 8) {
            FragA a0, a1; FragB b;
            wmma::load_matrix_sync(a0, pA + kk, 40);
            wmma::load_matrix_sync(a1, pA + 16 * 40 + kk, 40);
            wmma::load_matrix_sync(b, pB + kk, 40);
#pragma unroll
            for (int i = 0; i < a0.num_elements; i++) {
                a0.x[i] = wmma::__float_to_tf32(a0.x[i]);
                a1.x[i] = wmma::__float_to_tf32(a1.x[i]);
            }
#pragma unroll
            for (int i = 0; i < b.num_elements; i++) b.x[i] = wmma::__float_to_tf32(b.x[i]);
            wmma::mma_sync(acc0, a0, b, acc0);
            wmma::mma_sync(acc1, a1, b, acc1);
        }
        __syncthreads();
    }

    if (gateMode) {
        float* gsm = &sA[0][0];  // 64 x 72 (4608 floats, fits in sA's 5120)
        wmma::store_matrix_sync(gsm + (wm * 32) * 72 + wn * 16, acc0, 72, wmma::mem_row_major);
        wmma::store_matrix_sync(gsm + (wm * 32 + 16) * 72 + wn * 16, acc1, 72, wmma::mem_row_major);
        __syncthreads();
#pragma unroll
        for (int e = tid; e < 1024; e += 256) {
            int m = e >> 4, j = e & 15, n = n0 + j;
            float iv = gsm[m * 72 + j]      + bi[n]           + bh[n];
            float fv = gsm[m * 72 + 16 + j] + bi[H_ + n]      + bh[H_ + n];
            float gv = gsm[m * 72 + 32 + j] + bi[2 * H_ + n]  + bh[2 * H_ + n];
            float ov = gsm[m * 72 + 48 + j] + bi[3 * H_ + n]  + bh[3 * H_ + n];
            float cp = cprev[(size_t)m * H_ + n];
            float c2 = sigf(fv) * cp + sigf(iv) * tanhf(gv);
            cout[(size_t)m * H_ + n] = c2;
            hout[(size_t)m * H_ + n] = sigf(ov) * tanhf(c2);
        }
    } else {
#pragma unroll
        for (int i = 0; i < acc0.num_elements; i++) {
            acc0.x[i] = tanhf(acc0.x[i]);
            acc1.x[i] = tanhf(acc1.x[i]);
        }
        wmma::store_matrix_sync(hout + (size_t)(wm * 32) * H_ + n0 + wn * 16, acc0, H_, wmma::mem_row_major);
        wmma::store_matrix_sync(hout + (size_t)(wm * 32 + 16) * H_ + n0 + wn * 16, acc1, H_, wmma::mem_row_major);
    }
}

// ============ ctx projection (one-time): ctx_p[b,s,d] = sum_k context[s,b,k]*W_a[k,d] ============
__global__ __launch_bounds__(128) void ctxp_kernel(const float* __restrict__ ctx,
                                                   const float* __restrict__ Wa) {
    int w = threadIdx.x >> 5;
    int d0 = blockIdx.x * 64 + w * 16;
    int s0 = blockIdx.y * 64;
    int b  = blockIdx.z;

    FragC acc[4];
#pragma unroll
    for (int i = 0; i < 4; i++) wmma::fill_fragment(acc[i], 0.f);

    FragA af; FragBr bf;
    for (int k = 0; k < H_; k += 8) {
        wmma::load_matrix_sync(bf, Wa + (size_t)k * H_ + d0, H_);
#pragma unroll
        for (int i = 0; i < bf.num_elements; i++) bf.x[i] = wmma::__float_to_tf32(bf.x[i]);
#pragma unroll
        for (int fi = 0; fi < 4; fi++) {
            const float* ap = ctx + ((size_t)(s0 + fi * 16) * B_ + b) * H_ + k;
            wmma::load_matrix_sync(af, ap, B_ * H_);
#pragma unroll
            for (int i = 0; i < af.num_elements; i++) af.x[i] = wmma::__float_to_tf32(af.x[i]);
            wmma::mma_sync(acc[fi], af, bf, acc[fi]);
        }
    }
#pragma unroll
    for (int fi = 0; fi < 4; fi++) {
        float* op = g_ctxp + ((size_t)b * S_ + s0 + fi * 16) * H_ + d0;
        wmma::store_matrix_sync(op, acc[fi], H_, wmma::mem_row_major);
    }
}

// ============ attention scores: grid (4, B), 256 thr; CTA -> 32 scores ============
__global__ __launch_bounds__(256) void score_kernel(const float* __restrict__ h1) {
    __shared__ __align__(16) float h1s[H_];
    int b = blockIdx.y, q = blockIdx.x, tid = threadIdx.x;
    ((float4*)h1s)[tid] = ((const float4*)(h1 + (size_t)b * H_))[tid];
    __syncthreads();
    int w = tid >> 5, l = tid & 31;
    const float4* h4 = (const float4*)h1s;
#pragma unroll
    for (int i = 0; i < 4; i++) {
        int s = q * 32 + w * 4 + i;
        const float4* row = (const float4*)(g_ctxp + ((size_t)b * S_ + s) * H_);
        float acc = 0.f;
#pragma unroll
        for (int j = 0; j < 8; j++) {
            float4 a = h4[j * 32 + l], c = row[j * 32 + l];
            acc += a.x * c.x + a.y * c.y + a.z * c.z + a.w * c.w;
        }
#pragma unroll
        for (int o = 16; o > 0; o >>= 1) acc += __shfl_xor_sync(0xFFFFFFFFu, acc, o);
        if (!l) g_scores[b * S_ + s] = acc;
    }
}

// ============ softmax + context vector: grid (4, B), 256 thr; CTA -> 256 dims ============
__global__ __launch_bounds__(256) void softcvec_kernel(const float* __restrict__ ctx,
                                                       float* __restrict__ attns_t) {
    __shared__ float sc[S_];
    __shared__ float sal[S_];
    __shared__ float red[8];
    int b = blockIdx.y, q = blockIdx.x, tid = threadIdx.x;
    int w = tid >> 5, l = tid & 31;

    if (tid < 128) sc[tid] = g_scores[b * S_ + tid];
    __syncthreads();

    float mx = -3.4e38f;
    if (tid < 128) mx = sc[tid];
#pragma unroll
    for (int o = 16; o > 0; o >>= 1) mx = fmaxf(mx, __shfl_xor_sync(0xFFFFFFFFu, mx, o));
    if (tid < 128 && !l) red[w] = mx;
    __syncthreads();
    float gmx = fmaxf(fmaxf(red[0], red[1]), fmaxf(red[2], red[3]));
    float e = 0.f;
    if (tid < 128) { e = expf(sc[tid] - gmx); sal[tid] = e; }
    float se = e;
#pragma unroll
    for (int o = 16; o > 0; o >>= 1) se += __shfl_xor_sync(0xFFFFFFFFu, se, o);
    if (tid < 128 && !l) red[4 + w] = se;
    __syncthreads();
    float inv = 1.f / (red[4] + red[5] + red[6] + red[7]);
    if (tid < 128) {
        float a = sal[tid] * inv;
        sal[tid] = a;
        if (q == 0) attns_t[(size_t)b * S_ + tid] = a;
    }
    __syncthreads();

    int d = q * 256 + tid;
    float acc = 0.f;
#pragma unroll 4
    for (int s = 0; s < S_; s++) acc += sal[s] * ctx[((size_t)s * B_ + b) * H_ + d];
    g_cvec[(size_t)b * H_ + d] = acc;
}

// ============ finalize ============
__global__ __launch_bounds__(256) void finalize_kernel(float* __restrict__ hF, float* __restrict__ cF) {
    int i = blockIdx.x * blockDim.x + threadIdx.x;
    if (i < BH_) {
        hF[i]       = g_hb0[i];
        hF[BH_ + i] = g_hb1[i];
        cF[i]       = g_cb0[i];
        cF[BH_ + i] = g_cb1[i];
    }
}

// ============ host launcher ============
extern "C" void kernel_launch(void* const* d_in, const int* in_sizes, int n_in,
                              void* d_out, int out_size) {
    const float* inp   = (const float*)d_in[0];
    const float* ctx   = (const float*)d_in[1];
    const float* h0in  = (const float*)d_in[2];
    const float* c0in  = (const float*)d_in[3];
    const float* W_ih0 = (const float*)d_in[4];
    const float* b_ih0 = (const float*)d_in[5];
    const float* W_hh0 = (const float*)d_in[6];
    const float* b_hh0 = (const float*)d_in[7];
    const float* W_ih1 = (const float*)d_in[8];
    const float* b_ih1 = (const float*)d_in[9];
    const float* W_hh1 = (const float*)d_in[10];
    const float* b_hh1 = (const float*)d_in[11];
    const float* W_a   = (const float*)d_in[12];
    const float* W_out = (const float*)d_in[13];

    float* out   = (float*)d_out;
    float* outs  = out;                 // (T,B,H)
    float* hF    = out + TBH_;          // (2,B,H)
    float* cF    = hF + 2 * BH_;        // (2,B,H)
    float* attns = cF + 2 * BH_;        // (T,B,S)

    float *hb0, *hb1, *cb0, *cb1, *cvec, *zeros;
    cudaGetSymbolAddress((void**)&hb0, g_hb0);
    cudaGetSymbolAddress((void**)&hb1, g_hb1);
    cudaGetSymbolAddress((void**)&cb0, g_cb0);
    cudaGetSymbolAddress((void**)&cb1, g_cb1);
    cudaGetSymbolAddress((void**)&cvec, g_cvec);
    cudaGetSymbolAddress((void**)&zeros, g_zeros);

    dim3 g0(H_ / 64, S_ / 64, B_);
    ctxp_kernel<<<g0, 128>>>(ctx, W_a);

    for (int t = 0; t < T_; t++) {
        const float* feed = t ? outs + (size_t)(t - 1) * B_ * H_ : zeros;
        const float* h0p  = t ? hb0 + (size_t)(t & 1) * BH_ : h0in;
        const float* h1p  = t ? hb1 + (size_t)(t & 1) * BH_ : h0in + BH_;
        const float* c0p  = t ? cb0 : c0in;
        const float* c1p  = t ? cb1 : c0in + BH_;
        float* h0n = hb0 + (size_t)((t + 1) & 1) * BH_;
        float* h1n = hb1 + (size_t)((t + 1) & 1) * BH_;

        // layer 0: gates = [emb, feed] @ W_ih0^T + h0 @ W_hh0^T
        gemm_kernel<<<64, 256>>>(
            inp + (size_t)t * B_ * E_, E_, W_ih0,      EH_, E_ / 32,
            feed,                      H_, W_ih0 + E_, EH_, H_ / 32,
            h0p,                       H_, W_hh0,      H_,  H_ / 32,
            1, b_ih0, b_hh0, c0p, cb0, h0n);

        // layer 1: gates = h0n @ W_ih1^T + h1 @ W_hh1^T
        gemm_kernel<<<64, 256>>>(
            h0n, H_, W_ih1, H_, H_ / 32,
            h1p, H_, W_hh1, H_, H_ / 32,
            h0n, H_, W_hh1, H_, 0,
            1, b_ih1, b_hh1, c1p, cb1, h1n);

        // attention
        score_kernel<<<dim3(4, B_), 256>>>(h1n);
        softcvec_kernel<<<dim3(4, B_), 256>>>(ctx, attns + (size_t)t * B_ * S_);

        // output projection: attn_h = tanh([cvec, h1] @ W_out^T)
        gemm_kernel<<<16, 256>>>(
            cvec, H_, W_out,      2 * H_, H_ / 32,
            h1n,  H_, W_out + H_, 2 * H_, H_ / 32,
            h1n,  H_, W_out,      2 * H_, 0,
            0, b_ih0, b_hh0, c0p, cb0, outs + (size_t)t * B_ * H_);
    }

    finalize_kernel<<<(BH_ + 255) / 256, 256>>>(hF, cF);
}

// round 5
// speedup vs baseline: 2.3503x; 1.2527x over previous
#include <cuda_runtime.h>
#include <mma.h>
#include <math.h>

using namespace nvcuda;

#define T_  64
#define B_  64
#define S_  128
#define E_  512
#define H_  1024
#define EH_ 1536
#define BH_ (B_*H_)
#define TBH_ ((size_t)T_*B_*H_)

// ---------------- scratch (device globals; zero-init) ----------------
__device__ __align__(16) float g_wih0[(size_t)4*H_*EH_];
__device__ __align__(16) float g_whh0[(size_t)4*H_*H_];
__device__ __align__(16) float g_wih1[(size_t)4*H_*H_];
__device__ __align__(16) float g_whh1[(size_t)4*H_*H_];
__device__ __align__(16) float g_wa[(size_t)H_*H_];
__device__ __align__(16) float g_wout[(size_t)H_*2*H_];
__device__ __align__(16) float g_inp[(size_t)T_*B_*E_];
__device__ __align__(16) float g_hb0[2*BH_];     // layer0 h ping-pong (tf32-rounded)
__device__ __align__(16) float g_hb1[2*BH_];     // layer1 h ping-pong (tf32-rounded)
__device__ __align__(16) float g_hraw0[BH_];     // unrounded h (for hF output)
__device__ __align__(16) float g_hraw1[BH_];
__device__ __align__(16) float g_cb0[BH_];
__device__ __align__(16) float g_cb1[BH_];
__device__ __align__(16) float g_q[BH_];         // W_a @ h1 per batch
__device__ __align__(16) float g_cvec[BH_];      // tf32-rounded
__device__ __align__(16) float g_feed[BH_];      // tf32-rounded tanh outputs
__device__ __align__(16) float g_zeros[BH_];     // never written -> 0

__device__ __forceinline__ float sigf(float x) { return 1.f / (1.f + expf(-x)); }

__device__ __forceinline__ void cp16(float* dst, const float* src) {
    unsigned s = (unsigned)__cvta_generic_to_shared(dst);
    asm volatile("cp.async.cg.shared.global [%0], [%1], 16;\n" :: "r"(s), "l"(src));
}

using FragA = wmma::fragment<wmma::matrix_a, 16, 16, 8, wmma::precision::tf32, wmma::row_major>;
using FragB = wmma::fragment<wmma::matrix_b, 16, 16, 8, wmma::precision::tf32, wmma::col_major>;
using FragC = wmma::fragment<wmma::accumulator, 16, 16, 8, float>;

// ---------------- prep: round weights to tf32 scratch copies ----------------
__global__ __launch_bounds__(512) void prep_weights(
    const float* __restrict__ wih0, const float* __restrict__ whh0,
    const float* __restrict__ wih1, const float* __restrict__ whh1,
    const float* __restrict__ wa,   const float* __restrict__ wout) {
    const size_t n0 = (size_t)4 * H_ * EH_;
    const size_t n1 = (size_t)4 * H_ * H_;
    const size_t n2 = (size_t)H_ * H_;
    const size_t n3 = (size_t)H_ * 2 * H_;
    const size_t tot = n0 + 3 * n1 + n2 + n3;
    for (size_t i = (size_t)blockIdx.x * blockDim.x + threadIdx.x; i < tot;
         i += (size_t)gridDim.x * blockDim.x) {
        size_t j = i; float v; float* d;
        if (j < n0) { v = wih0[j]; d = g_wih0 + j; }
        else { j -= n0;
        if (j < n1) { v = whh0[j]; d = g_whh0 + j; }
        else { j -= n1;
        if (j < n1) { v = wih1[j]; d = g_wih1 + j; }
        else { j -= n1;
        if (j < n1) { v = whh1[j]; d = g_whh1 + j; }
        else { j -= n1;
        if (j < n2) { v = wa[j];   d = g_wa + j; }
        else { j -= n2; v = wout[j]; d = g_wout + j; } } } } }
        *d = wmma::__float_to_tf32(v);
    }
}

// ---------------- prep: round inp, init h/c states ----------------
__global__ __launch_bounds__(512) void prep_state(const float* __restrict__ inp,
                                                  const float* __restrict__ h0,
                                                  const float* __restrict__ c0) {
    const size_t ninp = (size_t)T_ * B_ * E_;
    const size_t tot = ninp + 2 * BH_;
    for (size_t i = (size_t)blockIdx.x * blockDim.x + threadIdx.x; i < tot;
         i += (size_t)gridDim.x * blockDim.x) {
        if (i < ninp) g_inp[i] = wmma::__float_to_tf32(inp[i]);
        else {
            size_t j = i - ninp;
            if (j < BH_) { g_hb0[j] = wmma::__float_to_tf32(h0[j]); g_cb0[j] = c0[j]; }
            else { j -= BH_; g_hb1[j] = wmma::__float_to_tf32(h0[BH_ + j]); g_cb1[j] = c0[BH_ + j]; }
        }
    }
}

// ---------------- main GEMM ----------------
// C(64, 64 cols) = sum_seg A_seg(64,K) @ W_seg(cols,K)^T. All inputs tf32-pre-rounded.
// mode 1: cols = {g*H + n0 + j} (4 gates x 16), LSTM cell epilogue.
// mode 0: cols contiguous (blockIdx*64), tanh -> hout (fp32) + rounded -> g_feed.
// mode 2: cols contiguous, plain store -> hout.
#define STG_ 5120   // floats per stage: A 64x40 + W 64x40
__global__ __launch_bounds__(256) void gemm_kernel(
    const float* __restrict__ A0, int lda0, const float* __restrict__ W0, int ldw0, int kt0,
    const float* __restrict__ A1, int lda1, const float* __restrict__ W1, int ldw1, int kt1,
    const float* __restrict__ A2, int lda2, const float* __restrict__ W2, int ldw2, int kt2,
    int mode,
    const float* __restrict__ bi, const float* __restrict__ bh,
    const float* __restrict__ cprev, float* __restrict__ cout,
    float* __restrict__ hout, float* __restrict__ hraw) {

    extern __shared__ __align__(16) float sm[];   // 4 stages * STG_ floats

    const int tid = threadIdx.x;
    const int w = tid >> 5;
    const int wm = w >> 2, wn = w & 3;
    const int n0 = blockIdx.x * (mode == 1 ? 16 : 64);

    // per-thread copy map: chunks q = tid + {0,256} -> A, tid + {512,768} -> W
    const int rA0 = (tid) >> 3,        cA0 = ((tid) & 7) * 4;
    const int rA1 = (tid + 256) >> 3,  cA1 = ((tid + 256) & 7) * 4;
    const int rW0 = (tid) >> 3,        cW0 = cA0;   // W chunk index = tid, tid+256 within 512
    const int rW1 = (tid + 256) >> 3,  cW1 = cA1;
    const int wr0 = (mode == 1) ? ((rW0 >> 4) * H_ + n0 + (rW0 & 15)) : (n0 + rW0);
    const int wr1 = (mode == 1) ? ((rW1 >> 4) * H_ + n0 + (rW1 & 15)) : (n0 + rW1);

    const float* segA[3] = {A0, A1, A2}; int slda[3] = {lda0, lda1, lda2};
    const float* segW[3] = {W0, W1, W2}; int sldw[3] = {ldw0, ldw1, ldw2};
    int skt[3] = {kt0, kt1, kt2};
    const int tot = kt0 + kt1 + kt2;

    int is = 0, ik = 0;
    auto issue = [&](int buf) {
        const float* Ab = segA[is]; const int la = slda[is];
        const float* Wb = segW[is]; const int lw = sldw[is];
        const int ko = ik * 32;
        float* st = sm + buf * STG_;
        cp16(st + rA0 * 40 + cA0,        Ab + (size_t)rA0 * la + ko + cA0);
        cp16(st + rA1 * 40 + cA1,        Ab + (size_t)rA1 * la + ko + cA1);
        cp16(st + 2560 + rW0 * 40 + cW0, Wb + (size_t)wr0 * lw + ko + cW0);
        cp16(st + 2560 + rW1 * 40 + cW1, Wb + (size_t)wr1 * lw + ko + cW1);
        asm volatile("cp.async.commit_group;\n");
        if (++ik == skt[is]) { ik = 0; ++is; }
    };

    FragC acc0, acc1;
    wmma::fill_fragment(acc0, 0.f);
    wmma::fill_fragment(acc1, 0.f);

    const int npro = tot < 3 ? tot : 3;
    for (int s = 0; s < npro; s++) issue(s);

    for (int i = 0; i < tot; i++) {
        const int rem = tot - 1 - i;
        if (rem >= 2)      asm volatile("cp.async.wait_group 2;\n");
        else if (rem == 1) asm volatile("cp.async.wait_group 1;\n");
        else               asm volatile("cp.async.wait_group 0;\n");
        __syncthreads();
        if (i + 3 < tot) issue((i + 3) & 3);

        const float* pA = sm + (i & 3) * STG_ + wm * 32 * 40;
        const float* pB = sm + (i & 3) * STG_ + 2560 + wn * 16 * 40;
#pragma unroll
        for (int kk = 0; kk < 32; kk += 8) {
            FragA a0, a1; FragB b;
            wmma::load_matrix_sync(a0, pA + kk, 40);
            wmma::load_matrix_sync(a1, pA + 16 * 40 + kk, 40);
            wmma::load_matrix_sync(b, pB + kk, 40);
            wmma::mma_sync(acc0, a0, b, acc0);
            wmma::mma_sync(acc1, a1, b, acc1);
        }
    }
    __syncthreads();

    if (mode == 1) {
        float* gsm = sm;   // 64 x 72 gate tile (buf0 region; last compute buf is 3)
        wmma::store_matrix_sync(gsm + (wm * 32) * 72 + wn * 16, acc0, 72, wmma::mem_row_major);
        wmma::store_matrix_sync(gsm + (wm * 32 + 16) * 72 + wn * 16, acc1, 72, wmma::mem_row_major);
        __syncthreads();
#pragma unroll
        for (int e = tid; e < 1024; e += 256) {
            int m = e >> 4, j = e & 15, n = n0 + j;
            float iv = gsm[m * 72 + j]      + bi[n]          + bh[n];
            float fv = gsm[m * 72 + 16 + j] + bi[H_ + n]     + bh[H_ + n];
            float gv = gsm[m * 72 + 32 + j] + bi[2 * H_ + n] + bh[2 * H_ + n];
            float ov = gsm[m * 72 + 48 + j] + bi[3 * H_ + n] + bh[3 * H_ + n];
            float cp = cprev[(size_t)m * H_ + n];
            float c2 = sigf(fv) * cp + sigf(iv) * tanhf(gv);
            float h2 = sigf(ov) * tanhf(c2);
            cout[(size_t)m * H_ + n] = c2;
            hraw[(size_t)m * H_ + n] = h2;
            hout[(size_t)m * H_ + n] = wmma::__float_to_tf32(h2);
        }
    } else if (mode == 0) {
#pragma unroll
        for (int i = 0; i < acc0.num_elements; i++) {
            acc0.x[i] = tanhf(acc0.x[i]);
            acc1.x[i] = tanhf(acc1.x[i]);
        }
        wmma::store_matrix_sync(hout + (size_t)(wm * 32) * H_ + n0 + wn * 16, acc0, H_, wmma::mem_row_major);
        wmma::store_matrix_sync(hout + (size_t)(wm * 32 + 16) * H_ + n0 + wn * 16, acc1, H_, wmma::mem_row_major);
#pragma unroll
        for (int i = 0; i < acc0.num_elements; i++) {
            acc0.x[i] = wmma::__float_to_tf32(acc0.x[i]);
            acc1.x[i] = wmma::__float_to_tf32(acc1.x[i]);
        }
        wmma::store_matrix_sync(g_feed + (size_t)(wm * 32) * H_ + n0 + wn * 16, acc0, H_, wmma::mem_row_major);
        wmma::store_matrix_sync(g_feed + (size_t)(wm * 32 + 16) * H_ + n0 + wn * 16, acc1, H_, wmma::mem_row_major);
    } else {
        wmma::store_matrix_sync(hout + (size_t)(wm * 32) * H_ + n0 + wn * 16, acc0, H_, wmma::mem_row_major);
        wmma::store_matrix_sync(hout + (size_t)(wm * 32 + 16) * H_ + n0 + wn * 16, acc1, H_, wmma::mem_row_major);
    }
}

// ---------------- fused attention: scores + softmax + cvec (CTA per batch) ----------------
__global__ __launch_bounds__(512) void attn_kernel(const float* __restrict__ ctx,
                                                   float* __restrict__ attns_t) {
    __shared__ __align__(16) float qs[H_];
    __shared__ float sc[S_];
    __shared__ float sal[S_];
    __shared__ float red[8];

    const int b = blockIdx.x, tid = threadIdx.x;
    const int w = tid >> 5, l = tid & 31;

    ((float2*)qs)[tid] = ((const float2*)(g_q + (size_t)b * H_))[tid];
    __syncthreads();

    // scores: 16 warps x 8 s
    const float4* q4 = (const float4*)qs;
#pragma unroll
    for (int i = 0; i < 8; i++) {
        const int s = w * 8 + i;
        const float4* row = (const float4*)(ctx + ((size_t)s * B_ + b) * H_);
        float acc = 0.f;
#pragma unroll
        for (int j = 0; j < 8; j++) {
            float4 a = q4[j * 32 + l], c = row[j * 32 + l];
            acc += a.x * c.x + a.y * c.y + a.z * c.z + a.w * c.w;
        }
#pragma unroll
        for (int o = 16; o > 0; o >>= 1) acc += __shfl_xor_sync(0xFFFFFFFFu, acc, o);
        if (!l) sc[s] = acc;
    }
    __syncthreads();

    // softmax over 128 scores (first 4 warps)
    float mx = -3.4e38f;
    if (tid < 128) mx = sc[tid];
#pragma unroll
    for (int o = 16; o > 0; o >>= 1) mx = fmaxf(mx, __shfl_xor_sync(0xFFFFFFFFu, mx, o));
    if (tid < 128 && !l) red[w] = mx;
    __syncthreads();
    const float gmx = fmaxf(fmaxf(red[0], red[1]), fmaxf(red[2], red[3]));
    float e = 0.f;
    if (tid < 128) { e = expf(sc[tid] - gmx); sal[tid] = e; }
    float se = e;
#pragma unroll
    for (int o = 16; o > 0; o >>= 1) se += __shfl_xor_sync(0xFFFFFFFFu, se, o);
    if (tid < 128 && !l) red[4 + w] = se;
    __syncthreads();
    const float inv = 1.f / (red[4] + red[5] + red[6] + red[7]);
    if (tid < 128) {
        float a = sal[tid] * inv;
        sal[tid] = a;
        attns_t[(size_t)b * S_ + tid] = a;
    }
    __syncthreads();

    // cvec: thread -> dim pair (2*tid, 2*tid+1), rounded for the outproj GEMM
    float2 acc = make_float2(0.f, 0.f);
#pragma unroll 4
    for (int s = 0; s < S_; s++) {
        const float a = sal[s];
        float2 c = *(const float2*)(ctx + ((size_t)s * B_ + b) * H_ + tid * 2);
        acc.x += a * c.x;
        acc.y += a * c.y;
    }
    g_cvec[(size_t)b * H_ + tid * 2]     = wmma::__float_to_tf32(acc.x);
    g_cvec[(size_t)b * H_ + tid * 2 + 1] = wmma::__float_to_tf32(acc.y);
}

// ---------------- finalize ----------------
__global__ __launch_bounds__(256) void finalize_kernel(float* __restrict__ hF, float* __restrict__ cF) {
    int i = blockIdx.x * blockDim.x + threadIdx.x;
    if (i < BH_) {
        hF[i]       = g_hraw0[i];
        hF[BH_ + i] = g_hraw1[i];
        cF[i]       = g_cb0[i];
        cF[BH_ + i] = g_cb1[i];
    }
}

// ---------------- host launcher ----------------
extern "C" void kernel_launch(void* const* d_in, const int* in_sizes, int n_in,
                              void* d_out, int out_size) {
    const float* inp   = (const float*)d_in[0];
    const float* ctx   = (const float*)d_in[1];
    const float* h0in  = (const float*)d_in[2];
    const float* c0in  = (const float*)d_in[3];
    const float* W_ih0 = (const float*)d_in[4];
    const float* b_ih0 = (const float*)d_in[5];
    const float* W_hh0 = (const float*)d_in[6];
    const float* b_hh0 = (const float*)d_in[7];
    const float* W_ih1 = (const float*)d_in[8];
    const float* b_ih1 = (const float*)d_in[9];
    const float* W_hh1 = (const float*)d_in[10];
    const float* b_hh1 = (const float*)d_in[11];
    const float* W_a   = (const float*)d_in[12];
    const float* W_out = (const float*)d_in[13];

    float* out   = (float*)d_out;
    float* outs  = out;                 // (T,B,H)
    float* hF    = out + TBH_;          // (2,B,H)
    float* cF    = hF + 2 * BH_;        // (2,B,H)
    float* attns = cF + 2 * BH_;        // (T,B,S)

    float *wih0, *whh0, *wih1, *whh1, *wa, *wout_s;
    float *ginp, *hb0, *hb1, *hraw0, *hraw1, *cb0, *cb1, *q, *cvec, *feed, *zeros;
    cudaGetSymbolAddress((void**)&wih0, g_wih0);
    cudaGetSymbolAddress((void**)&whh0, g_whh0);
    cudaGetSymbolAddress((void**)&wih1, g_wih1);
    cudaGetSymbolAddress((void**)&whh1, g_whh1);
    cudaGetSymbolAddress((void**)&wa, g_wa);
    cudaGetSymbolAddress((void**)&wout_s, g_wout);
    cudaGetSymbolAddress((void**)&ginp, g_inp);
    cudaGetSymbolAddress((void**)&hb0, g_hb0);
    cudaGetSymbolAddress((void**)&hb1, g_hb1);
    cudaGetSymbolAddress((void**)&hraw0, g_hraw0);
    cudaGetSymbolAddress((void**)&hraw1, g_hraw1);
    cudaGetSymbolAddress((void**)&cb0, g_cb0);
    cudaGetSymbolAddress((void**)&cb1, g_cb1);
    cudaGetSymbolAddress((void**)&q, g_q);
    cudaGetSymbolAddress((void**)&cvec, g_cvec);
    cudaGetSymbolAddress((void**)&feed, g_feed);
    cudaGetSymbolAddress((void**)&zeros, g_zeros);

    const int smemB = 4 * STG_ * sizeof(float);   // 81920
    static int attrSet = 0;
    if (!attrSet) {
        cudaFuncSetAttribute(gemm_kernel, cudaFuncAttributeMaxDynamicSharedMemorySize, smemB);
        attrSet = 1;
    }

    prep_weights<<<2048, 512>>>(W_ih0, W_hh0, W_ih1, W_hh1, W_a, W_out);
    prep_state<<<1024, 512>>>(inp, h0in, c0in);

    for (int t = 0; t < T_; t++) {
        const float* fd  = t ? feed : zeros;
        const float* h0p = hb0 + (size_t)(t & 1) * BH_;
        const float* h1p = hb1 + (size_t)(t & 1) * BH_;
        float* h0n = hb0 + (size_t)((t + 1) & 1) * BH_;
        float* h1n = hb1 + (size_t)((t + 1) & 1) * BH_;

        // layer 0: gates = [emb, feed] @ W_ih0^T + h0 @ W_hh0^T
        gemm_kernel<<<64, 256, smemB>>>(
            ginp + (size_t)t * B_ * E_, E_, wih0,       EH_, E_ / 32,
            fd,                         H_, wih0 + E_,  EH_, H_ / 32,
            h0p,                        H_, whh0,       H_,  H_ / 32,
            1, b_ih0, b_hh0, cb0, cb0, h0n, hraw0);

        // layer 1
        gemm_kernel<<<64, 256, smemB>>>(
            h0n, H_, wih1, H_, H_ / 32,
            h1p, H_, whh1, H_, H_ / 32,
            h0n, H_, whh1, H_, 0,
            1, b_ih1, b_hh1, cb1, cb1, h1n, hraw1);

        // q = h1 @ W_a^T
        gemm_kernel<<<16, 256, smemB>>>(
            h1n, H_, wa, H_, H_ / 32,
            h1n, H_, wa, H_, 0,
            h1n, H_, wa, H_, 0,
            2, b_ih0, b_hh0, cb0, cb0, q, hraw0);

        // attention: scores + softmax + cvec
        attn_kernel<<<B_, 512>>>(ctx, attns + (size_t)t * B_ * S_);

        // output projection: attn_h = tanh([cvec, h1] @ W_out^T); also writes g_feed
        gemm_kernel<<<16, 256, smemB>>>(
            cvec, H_, wout_s,      2 * H_, H_ / 32,
            h1n,  H_, wout_s + H_, 2 * H_, H_ / 32,
            h1n,  H_, wout_s,      2 * H_, 0,
            0, b_ih0, b_hh0, cb0, cb0, outs + (size_t)t * B_ * H_, hraw0);
    }

    finalize_kernel<<<(BH_ + 255) / 256, 256>>>(hF, cF);
}

// round 6
// speedup vs baseline: 4.1256x; 1.7554x over previous
#include <cuda_runtime.h>
#include <math.h>
#include <stdint.h>

#define T_  64
#define B_  64
#define S_  128
#define E_  512
#define H_  1024
#define EH_ 1536
#define BH_ (B_*H_)
#define TBH_ ((size_t)T_*B_*H_)
#define SPLIT_ 4

// ---------------- scratch (device globals; zero-init) ----------------
__device__ __align__(16) float g_wih0[(size_t)4*H_*EH_];
__device__ __align__(16) float g_whh0[(size_t)4*H_*H_];
__device__ __align__(16) float g_wih1[(size_t)4*H_*H_];
__device__ __align__(16) float g_whh1[(size_t)4*H_*H_];
__device__ __align__(16) float g_wa[(size_t)H_*H_];
__device__ __align__(16) float g_wout[(size_t)H_*2*H_];
__device__ __align__(16) float g_inp[(size_t)T_*B_*E_];
__device__ __align__(16) float g_hb0[2*BH_];     // layer0 h ping-pong (tf32-rounded)
__device__ __align__(16) float g_hb1[2*BH_];
__device__ __align__(16) float g_hraw0[BH_];     // unrounded h for hF
__device__ __align__(16) float g_hraw1[BH_];
__device__ __align__(16) float g_cb0[BH_];
__device__ __align__(16) float g_cb1[BH_];
__device__ __align__(16) float g_q[BH_];
__device__ __align__(16) float g_cvec[BH_];      // tf32-rounded
__device__ __align__(16) float g_feed[BH_];      // tf32-rounded tanh outputs
__device__ __align__(16) float g_scores[B_*S_];
__device__ __align__(16) float g_part[(size_t)256*4096];  // split-K partials
__device__ int g_cnt[64];                        // split-K arrival counters
__device__ __align__(16) float g_zeros[BH_];     // never written -> 0

__device__ __forceinline__ float sigf(float x) { return 1.f / (1.f + expf(-x)); }

__device__ __forceinline__ float to_tf32(float x) {
    uint32_t r;
    asm("cvt.rna.tf32.f32 %0, %1;" : "=r"(r) : "f"(x));
    return __uint_as_float(r);
}

__device__ __forceinline__ void cp16(float* dst, const float* src) {
    unsigned s = (unsigned)__cvta_generic_to_shared(dst);
    asm volatile("cp.async.cg.shared.global [%0], [%1], 16;\n" :: "r"(s), "l"(src));
}

__device__ __forceinline__ void mma8(float* c, const uint32_t* a, const uint32_t* b) {
    asm volatile(
        "mma.sync.aligned.m16n8k8.row.col.f32.tf32.tf32.f32 "
        "{%0,%1,%2,%3}, {%4,%5,%6,%7}, {%8,%9}, {%0,%1,%2,%3};\n"
        : "+f"(c[0]), "+f"(c[1]), "+f"(c[2]), "+f"(c[3])
        : "r"(a[0]), "r"(a[1]), "r"(a[2]), "r"(a[3]), "r"(b[0]), "r"(b[1]));
}

// ---------------- prep kernels ----------------
__global__ __launch_bounds__(512) void prep_weights(
    const float* __restrict__ wih0, const float* __restrict__ whh0,
    const float* __restrict__ wih1, const float* __restrict__ whh1,
    const float* __restrict__ wa,   const float* __restrict__ wout) {
    const size_t n0 = (size_t)4 * H_ * EH_;
    const size_t n1 = (size_t)4 * H_ * H_;
    const size_t n2 = (size_t)H_ * H_;
    const size_t n3 = (size_t)H_ * 2 * H_;
    const size_t tot = n0 + 3 * n1 + n2 + n3;
    for (size_t i = (size_t)blockIdx.x * blockDim.x + threadIdx.x; i < tot;
         i += (size_t)gridDim.x * blockDim.x) {
        size_t j = i; float v; float* d;
        if (j < n0) { v = wih0[j]; d = g_wih0 + j; }
        else { j -= n0;
        if (j < n1) { v = whh0[j]; d = g_whh0 + j; }
        else { j -= n1;
        if (j < n1) { v = wih1[j]; d = g_wih1 + j; }
        else { j -= n1;
        if (j < n1) { v = whh1[j]; d = g_whh1 + j; }
        else { j -= n1;
        if (j < n2) { v = wa[j];   d = g_wa + j; }
        else { j -= n2; v = wout[j]; d = g_wout + j; } } } } }
        *d = to_tf32(v);
    }
}

__global__ __launch_bounds__(512) void prep_state(const float* __restrict__ inp,
                                                  const float* __restrict__ h0,
                                                  const float* __restrict__ c0) {
    const size_t ninp = (size_t)T_ * B_ * E_;
    const size_t tot = ninp + 2 * BH_;
    for (size_t i = (size_t)blockIdx.x * blockDim.x + threadIdx.x; i < tot;
         i += (size_t)gridDim.x * blockDim.x) {
        if (i < ninp) g_inp[i] = to_tf32(inp[i]);
        else {
            size_t j = i - ninp;
            if (j < BH_) { g_hb0[j] = to_tf32(h0[j]); g_cb0[j] = c0[j]; }
            else { j -= BH_; g_hb1[j] = to_tf32(h0[BH_ + j]); g_cb1[j] = c0[BH_ + j]; }
        }
    }
}

// ---------------- split-K GEMM with last-CTA epilogue ----------------
// C(64 x 64 cols) = sum_seg A_seg(64,K) @ W_seg(cols,K)^T, tf32 mma, fp32 acc.
// grid = NGRP * SPLIT_; grp = blockIdx.x / SPLIT_. Each CTA does cpk 32-wide K chunks.
// mode 1: cols {gate*H + n0 + j} (n0=grp*16), LSTM cell epilogue.
// mode 0: cols n0..n0+63 (n0=grp*64), tanh -> hout + rounded -> g_feed.
// mode 2: cols contiguous, plain store -> hout.
#define STRD_ 36
#define STGF_ (64*STRD_*2)   // 4608 floats per stage (A + W)
__global__ __launch_bounds__(128, 4) void gemm_kernel(
    const float* __restrict__ A0, int lda0, const float* __restrict__ W0, int ldw0, int kt0,
    const float* __restrict__ A1, int lda1, const float* __restrict__ W1, int ldw1, int kt1,
    const float* __restrict__ A2, int lda2, const float* __restrict__ W2, int ldw2, int kt2,
    int mode,
    const float* __restrict__ bi, const float* __restrict__ bh,
    const float* __restrict__ cprev, float* __restrict__ cout,
    float* __restrict__ hout, float* __restrict__ hraw) {

    extern __shared__ __align__(16) float sm[];   // 3 stages * STGF_

    const int tid = threadIdx.x;
    const int w = tid >> 5, lane = tid & 31;
    const int wm = w >> 1, wn = w & 1;
    const int g8 = lane >> 2, tg = lane & 3;
    const int grp = blockIdx.x / SPLIT_;
    const int sk  = blockIdx.x % SPLIT_;
    const int n0  = grp * (mode == 1 ? 16 : 64);

    const int tot = kt0 + kt1 + kt2;
    const int cpk = tot / SPLIT_;
    const int cbase = sk * cpk;

    // per-thread copy coords (4 16B chunks for A, 4 for W per stage)
    int rr[4], cc4[4], wr[4];
#pragma unroll
    for (int j = 0; j < 4; j++) {
        int q = j * 128 + tid;
        rr[j] = q >> 3; cc4[j] = (q & 7) * 4;
        wr[j] = (mode == 1) ? ((rr[j] >> 4) * H_ + n0 + (rr[j] & 15)) : (n0 + rr[j]);
    }

    auto issue = [&](int c, int buf) {
        const float* Ab; const float* Wb; int la, lw, ko;
        if (c < kt0)            { Ab = A0; Wb = W0; la = lda0; lw = ldw0; ko = c * 32; }
        else if (c < kt0 + kt1) { Ab = A1; Wb = W1; la = lda1; lw = ldw1; ko = (c - kt0) * 32; }
        else                    { Ab = A2; Wb = W2; la = lda2; lw = ldw2; ko = (c - kt0 - kt1) * 32; }
        float* st = sm + buf * STGF_;
#pragma unroll
        for (int j = 0; j < 4; j++)
            cp16(st + rr[j] * STRD_ + cc4[j], Ab + (size_t)rr[j] * la + ko + cc4[j]);
#pragma unroll
        for (int j = 0; j < 4; j++)
            cp16(st + 64 * STRD_ + rr[j] * STRD_ + cc4[j], Wb + (size_t)wr[j] * lw + ko + cc4[j]);
        asm volatile("cp.async.commit_group;\n");
    };

    float acc[2][4][4];
#pragma unroll
    for (int mi = 0; mi < 2; mi++)
#pragma unroll
        for (int ni = 0; ni < 4; ni++)
#pragma unroll
            for (int e = 0; e < 4; e++) acc[mi][ni][e] = 0.f;

    issue(cbase, 0);
    if (cpk > 1) issue(cbase + 1, 1);

    for (int i = 0; i < cpk; i++) {
        if (i < cpk - 1) asm volatile("cp.async.wait_group 1;\n");
        else             asm volatile("cp.async.wait_group 0;\n");
        __syncthreads();
        if (i + 2 < cpk) issue(cbase + i + 2, (i + 2) % 3);

        const float* stg = sm + (i % 3) * STGF_;
        const uint32_t* pA = (const uint32_t*)stg + (wm * 32 + g8) * STRD_ + tg;
        const uint32_t* pB = (const uint32_t*)(stg + 64 * STRD_) + (wn * 32 + g8) * STRD_ + tg;
#pragma unroll
        for (int s = 0; s < 4; s++) {
            const int ko = s * 8;
            uint32_t a0[4], a1[4], b[4][2];
            a0[0] = pA[ko];               a0[1] = pA[8 * STRD_ + ko];
            a0[2] = pA[ko + 4];           a0[3] = pA[8 * STRD_ + ko + 4];
            a1[0] = pA[16 * STRD_ + ko];  a1[1] = pA[24 * STRD_ + ko];
            a1[2] = pA[16 * STRD_ + ko + 4]; a1[3] = pA[24 * STRD_ + ko + 4];
#pragma unroll
            for (int ni = 0; ni < 4; ni++) {
                b[ni][0] = pB[ni * 8 * STRD_ + ko];
                b[ni][1] = pB[ni * 8 * STRD_ + ko + 4];
            }
#pragma unroll
            for (int ni = 0; ni < 4; ni++) {
                mma8(acc[0][ni], a0, b[ni]);
                mma8(acc[1][ni], a1, b[ni]);
            }
        }
    }

    // write this CTA's 64x64 partial
    {
        float* pp = g_part + (size_t)blockIdx.x * 4096;
#pragma unroll
        for (int mi = 0; mi < 2; mi++)
#pragma unroll
            for (int ni = 0; ni < 4; ni++) {
                int r = wm * 32 + mi * 16 + g8, c = wn * 32 + ni * 8 + tg * 2;
                *(float2*)(pp + r * 64 + c)       = make_float2(acc[mi][ni][0], acc[mi][ni][1]);
                *(float2*)(pp + (r + 8) * 64 + c) = make_float2(acc[mi][ni][2], acc[mi][ni][3]);
            }
    }
    __threadfence();
    __syncthreads();

    __shared__ int isLast;
    if (tid == 0) {
        int old = atomicAdd(&g_cnt[grp], 1);
        isLast = (old == SPLIT_ - 1);
    }
    __syncthreads();
    if (!isLast) return;
    if (tid == 0) g_cnt[grp] = 0;
    __threadfence();

    // deterministic reduction of the 4 partials into smem
    float* red = sm;
    for (int e = tid; e < 1024; e += 128) {
        const float* p0 = g_part + (size_t)(grp * SPLIT_) * 4096 + e * 4;
        float4 v0 = *(const float4*)(p0);
        float4 v1 = *(const float4*)(p0 + 4096);
        float4 v2 = *(const float4*)(p0 + 8192);
        float4 v3 = *(const float4*)(p0 + 12288);
        float4 s;
        s.x = v0.x + v1.x + v2.x + v3.x;
        s.y = v0.y + v1.y + v2.y + v3.y;
        s.z = v0.z + v1.z + v2.z + v3.z;
        s.w = v0.w + v1.w + v2.w + v3.w;
        *(float4*)(red + e * 4) = s;
    }
    __syncthreads();

    if (mode == 1) {
        for (int e = tid; e < 1024; e += 128) {
            int m = e >> 4, j = e & 15, n = n0 + j;
            float iv = red[m * 64 + j]      + bi[n]           + bh[n];
            float fv = red[m * 64 + 16 + j] + bi[H_ + n]      + bh[H_ + n];
            float gv = red[m * 64 + 32 + j] + bi[2 * H_ + n]  + bh[2 * H_ + n];
            float ov = red[m * 64 + 48 + j] + bi[3 * H_ + n]  + bh[3 * H_ + n];
            float cp = cprev[(size_t)m * H_ + n];
            float c2 = sigf(fv) * cp + sigf(iv) * tanhf(gv);
            float h2 = sigf(ov) * tanhf(c2);
            cout[(size_t)m * H_ + n] = c2;
            hraw[(size_t)m * H_ + n] = h2;
            hout[(size_t)m * H_ + n] = to_tf32(h2);
        }
    } else if (mode == 0) {
        for (int e = tid; e < 4096; e += 128) {
            int m = e >> 6, c = e & 63;
            float v = tanhf(red[e]);
            hout[(size_t)m * H_ + n0 + c]   = v;
            g_feed[(size_t)m * H_ + n0 + c] = to_tf32(v);
        }
    } else {
        for (int e = tid; e < 4096; e += 128) {
            int m = e >> 6, c = e & 63;
            hout[(size_t)m * H_ + n0 + c] = red[e];
        }
    }
}

// ---------------- attention scores: grid (4, B), 256 thr ----------------
__global__ __launch_bounds__(256) void score_kernel(const float* __restrict__ ctx) {
    __shared__ __align__(16) float qs[H_];
    const int b = blockIdx.y, qd = blockIdx.x, tid = threadIdx.x;
    ((float4*)qs)[tid] = ((const float4*)(g_q + (size_t)b * H_))[tid];
    __syncthreads();
    const int w = tid >> 5, l = tid & 31;
    const float4* q4 = (const float4*)qs;
#pragma unroll
    for (int i = 0; i < 4; i++) {
        const int s = qd * 32 + w * 4 + i;
        const float4* row = (const float4*)(ctx + ((size_t)s * B_ + b) * H_);
        float acc = 0.f;
#pragma unroll
        for (int j = 0; j < 8; j++) {
            float4 a = q4[j * 32 + l], c = row[j * 32 + l];
            acc += a.x * c.x + a.y * c.y + a.z * c.z + a.w * c.w;
        }
#pragma unroll
        for (int o = 16; o > 0; o >>= 1) acc += __shfl_xor_sync(0xFFFFFFFFu, acc, o);
        if (!l) g_scores[b * S_ + s] = acc;
    }
}

// ---------------- softmax + cvec: grid (4, B), 256 thr ----------------
__global__ __launch_bounds__(256) void softcvec_kernel(const float* __restrict__ ctx,
                                                       float* __restrict__ attns_t) {
    __shared__ float sc[S_];
    __shared__ float sal[S_];
    __shared__ float red[8];
    const int b = blockIdx.y, qd = blockIdx.x, tid = threadIdx.x;
    const int w = tid >> 5, l = tid & 31;

    if (tid < 128) sc[tid] = g_scores[b * S_ + tid];
    __syncthreads();

    float mx = -3.4e38f;
    if (tid < 128) mx = sc[tid];
#pragma unroll
    for (int o = 16; o > 0; o >>= 1) mx = fmaxf(mx, __shfl_xor_sync(0xFFFFFFFFu, mx, o));
    if (tid < 128 && !l) red[w] = mx;
    __syncthreads();
    const float gmx = fmaxf(fmaxf(red[0], red[1]), fmaxf(red[2], red[3]));
    float e = 0.f;
    if (tid < 128) { e = expf(sc[tid] - gmx); sal[tid] = e; }
    float se = e;
#pragma unroll
    for (int o = 16; o > 0; o >>= 1) se += __shfl_xor_sync(0xFFFFFFFFu, se, o);
    if (tid < 128 && !l) red[4 + w] = se;
    __syncthreads();
    const float inv = 1.f / (red[4] + red[5] + red[6] + red[7]);
    if (tid < 128) {
        float a = sal[tid] * inv;
        sal[tid] = a;
        if (qd == 0) attns_t[(size_t)b * S_ + tid] = a;
    }
    __syncthreads();

    const int d = qd * 256 + tid;
    float acc = 0.f;
#pragma unroll 4
    for (int s = 0; s < S_; s++) acc += sal[s] * ctx[((size_t)s * B_ + b) * H_ + d];
    g_cvec[(size_t)b * H_ + d] = to_tf32(acc);
}

// ---------------- finalize ----------------
__global__ __launch_bounds__(256) void finalize_kernel(float* __restrict__ hF, float* __restrict__ cF) {
    int i = blockIdx.x * blockDim.x + threadIdx.x;
    if (i < BH_) {
        hF[i]       = g_hraw0[i];
        hF[BH_ + i] = g_hraw1[i];
        cF[i]       = g_cb0[i];
        cF[BH_ + i] = g_cb1[i];
    }
}

// ---------------- host launcher ----------------
extern "C" void kernel_launch(void* const* d_in, const int* in_sizes, int n_in,
                              void* d_out, int out_size) {
    const float* inp   = (const float*)d_in[0];
    const float* ctx   = (const float*)d_in[1];
    const float* h0in  = (const float*)d_in[2];
    const float* c0in  = (const float*)d_in[3];
    const float* W_ih0 = (const float*)d_in[4];
    const float* b_ih0 = (const float*)d_in[5];
    const float* W_hh0 = (const float*)d_in[6];
    const float* b_hh0 = (const float*)d_in[7];
    const float* W_ih1 = (const float*)d_in[8];
    const float* b_ih1 = (const float*)d_in[9];
    const float* W_hh1 = (const float*)d_in[10];
    const float* b_hh1 = (const float*)d_in[11];
    const float* W_a   = (const float*)d_in[12];
    const float* W_out = (const float*)d_in[13];

    float* out   = (float*)d_out;
    float* outs  = out;                 // (T,B,H)
    float* hF    = out + TBH_;          // (2,B,H)
    float* cF    = hF + 2 * BH_;        // (2,B,H)
    float* attns = cF + 2 * BH_;        // (T,B,S)

    float *wih0, *whh0, *wih1, *whh1, *wa, *wout_s;
    float *ginp, *hb0, *hb1, *hraw0, *hraw1, *cb0, *cb1, *q, *cvec, *feed, *zeros;
    cudaGetSymbolAddress((void**)&wih0, g_wih0);
    cudaGetSymbolAddress((void**)&whh0, g_whh0);
    cudaGetSymbolAddress((void**)&wih1, g_wih1);
    cudaGetSymbolAddress((void**)&whh1, g_whh1);
    cudaGetSymbolAddress((void**)&wa, g_wa);
    cudaGetSymbolAddress((void**)&wout_s, g_wout);
    cudaGetSymbolAddress((void**)&ginp, g_inp);
    cudaGetSymbolAddress((void**)&hb0, g_hb0);
    cudaGetSymbolAddress((void**)&hb1, g_hb1);
    cudaGetSymbolAddress((void**)&hraw0, g_hraw0);
    cudaGetSymbolAddress((void**)&hraw1, g_hraw1);
    cudaGetSymbolAddress((void**)&cb0, g_cb0);
    cudaGetSymbolAddress((void**)&cb1, g_cb1);
    cudaGetSymbolAddress((void**)&q, g_q);
    cudaGetSymbolAddress((void**)&cvec, g_cvec);
    cudaGetSymbolAddress((void**)&feed, g_feed);
    cudaGetSymbolAddress((void**)&zeros, g_zeros);

    const int smemB = 3 * STGF_ * sizeof(float);   // 55296
    static int attrSet = 0;
    if (!attrSet) {
        cudaFuncSetAttribute(gemm_kernel, cudaFuncAttributeMaxDynamicSharedMemorySize, smemB);
        attrSet = 1;
    }

    prep_weights<<<2048, 512>>>(W_ih0, W_hh0, W_ih1, W_hh1, W_a, W_out);
    prep_state<<<1024, 512>>>(inp, h0in, c0in);

    for (int t = 0; t < T_; t++) {
        const float* fd  = t ? feed : zeros;
        const float* h0p = hb0 + (size_t)(t & 1) * BH_;
        const float* h1p = hb1 + (size_t)(t & 1) * BH_;
        float* h0n = hb0 + (size_t)((t + 1) & 1) * BH_;
        float* h1n = hb1 + (size_t)((t + 1) & 1) * BH_;

        // layer 0: gates = [emb, feed] @ W_ih0^T + h0 @ W_hh0^T  (64 grp x 4 split)
        gemm_kernel<<<64 * SPLIT_, 128, smemB>>>(
            ginp + (size_t)t * B_ * E_, E_, wih0,       EH_, 16,
            fd,                         H_, wih0 + E_,  EH_, 32,
            h0p,                        H_, whh0,       H_,  32,
            1, b_ih0, b_hh0, cb0, cb0, h0n, hraw0);

        // layer 1
        gemm_kernel<<<64 * SPLIT_, 128, smemB>>>(
            h0n, H_, wih1, H_, 32,
            h1p, H_, whh1, H_, 32,
            h0n, H_, whh1, H_, 0,
            1, b_ih1, b_hh1, cb1, cb1, h1n, hraw1);

        // q = h1 @ W_a^T  (16 grp x 4 split)
        gemm_kernel<<<16 * SPLIT_, 128, smemB>>>(
            h1n, H_, wa, H_, 32,
            h1n, H_, wa, H_, 0,
            h1n, H_, wa, H_, 0,
            2, b_ih0, b_hh0, cb0, cb0, q, hraw0);

        // attention
        score_kernel<<<dim3(4, B_), 256>>>(ctx);
        softcvec_kernel<<<dim3(4, B_), 256>>>(ctx, attns + (size_t)t * B_ * S_);

        // output projection: attn_h = tanh([cvec, h1] @ W_out^T); also writes g_feed
        gemm_kernel<<<16 * SPLIT_, 128, smemB>>>(
            cvec, H_, wout_s,      2 * H_, 32,
            h1n,  H_, wout_s + H_, 2 * H_, 32,
            h1n,  H_, wout_s,      2 * H_, 0,
            0, b_ih0, b_hh0, cb0, cb0, outs + (size_t)t * B_ * H_, hraw0);
    }

    finalize_kernel<<<(BH_ + 255) / 256, 256>>>(hF, cF);
}

// round 7
// speedup vs baseline: 5.9728x; 1.4478x over previous
#include <cuda_runtime.h>
#include <math.h>
#include <stdint.h>

#define T_  64
#define B_  64
#define S_  128
#define E_  512
#define H_  1024
#define EH_ 1536
#define BH_ (B_*H_)
#define TBH_ ((size_t)T_*B_*H_)
#define SPLIT_ 8

// ---------------- scratch (device globals; zero-init) ----------------
__device__ __align__(16) float g_wih0[(size_t)4*H_*EH_];
__device__ __align__(16) float g_whh0[(size_t)4*H_*H_];
__device__ __align__(16) float g_wih1[(size_t)4*H_*H_];
__device__ __align__(16) float g_whh1[(size_t)4*H_*H_];
__device__ __align__(16) float g_wa[(size_t)H_*H_];
__device__ __align__(16) float g_wout[(size_t)H_*2*H_];
__device__ __align__(16) float g_inp[(size_t)T_*B_*E_];
__device__ __align__(16) float g_hb0[2*BH_];     // layer0 h ping-pong (tf32-rounded)
__device__ __align__(16) float g_hb1[2*BH_];
__device__ __align__(16) float g_hraw0[BH_];     // unrounded h for hF
__device__ __align__(16) float g_hraw1[BH_];
__device__ __align__(16) float g_cb0[BH_];
__device__ __align__(16) float g_cb1[BH_];
__device__ __align__(16) float g_q[BH_];
__device__ __align__(16) float g_cvec[BH_];      // tf32-rounded
__device__ __align__(16) float g_feed[BH_];      // tf32-rounded tanh outputs
__device__ __align__(16) float g_scores[B_*S_];
__device__ __align__(16) float g_part[(size_t)512*4096];  // split-K partials
__device__ int g_cnt[64];                        // split-K arrival counters
__device__ __align__(16) float g_zeros[BH_];     // never written -> 0

__device__ __forceinline__ float sigf(float x) { return 1.f / (1.f + expf(-x)); }

__device__ __forceinline__ float to_tf32(float x) {
    uint32_t r;
    asm("cvt.rna.tf32.f32 %0, %1;" : "=r"(r) : "f"(x));
    return __uint_as_float(r);
}

__device__ __forceinline__ void cp16(float* dst, const float* src) {
    unsigned s = (unsigned)__cvta_generic_to_shared(dst);
    asm volatile("cp.async.cg.shared.global [%0], [%1], 16;\n" :: "r"(s), "l"(src));
}

__device__ __forceinline__ void mma8(float* c, const uint32_t* a, const uint32_t* b) {
    asm volatile(
        "mma.sync.aligned.m16n8k8.row.col.f32.tf32.tf32.f32 "
        "{%0,%1,%2,%3}, {%4,%5,%6,%7}, {%8,%9}, {%0,%1,%2,%3};\n"
        : "+f"(c[0]), "+f"(c[1]), "+f"(c[2]), "+f"(c[3])
        : "r"(a[0]), "r"(a[1]), "r"(a[2]), "r"(a[3]), "r"(b[0]), "r"(b[1]));
}

// ---------------- prep kernels ----------------
__global__ __launch_bounds__(512) void prep_weights(
    const float* __restrict__ wih0, const float* __restrict__ whh0,
    const float* __restrict__ wih1, const float* __restrict__ whh1,
    const float* __restrict__ wa,   const float* __restrict__ wout) {
    const size_t n0 = (size_t)4 * H_ * EH_;
    const size_t n1 = (size_t)4 * H_ * H_;
    const size_t n2 = (size_t)H_ * H_;
    const size_t n3 = (size_t)H_ * 2 * H_;
    const size_t tot = n0 + 3 * n1 + n2 + n3;
    for (size_t i = (size_t)blockIdx.x * blockDim.x + threadIdx.x; i < tot;
         i += (size_t)gridDim.x * blockDim.x) {
        size_t j = i; float v; float* d;
        if (j < n0) { v = wih0[j]; d = g_wih0 + j; }
        else { j -= n0;
        if (j < n1) { v = whh0[j]; d = g_whh0 + j; }
        else { j -= n1;
        if (j < n1) { v = wih1[j]; d = g_wih1 + j; }
        else { j -= n1;
        if (j < n1) { v = whh1[j]; d = g_whh1 + j; }
        else { j -= n1;
        if (j < n2) { v = wa[j];   d = g_wa + j; }
        else { j -= n2; v = wout[j]; d = g_wout + j; } } } } }
        *d = to_tf32(v);
    }
}

__global__ __launch_bounds__(512) void prep_state(const float* __restrict__ inp,
                                                  const float* __restrict__ h0,
                                                  const float* __restrict__ c0) {
    const size_t ninp = (size_t)T_ * B_ * E_;
    const size_t tot = ninp + 2 * BH_;
    for (size_t i = (size_t)blockIdx.x * blockDim.x + threadIdx.x; i < tot;
         i += (size_t)gridDim.x * blockDim.x) {
        if (i < ninp) g_inp[i] = to_tf32(inp[i]);
        else {
            size_t j = i - ninp;
            if (j < BH_) { g_hb0[j] = to_tf32(h0[j]); g_cb0[j] = c0[j]; }
            else { j -= BH_; g_hb1[j] = to_tf32(h0[BH_ + j]); g_cb1[j] = c0[BH_ + j]; }
        }
    }
}

// ---------------- split-K GEMM with last-CTA epilogue ----------------
// C(64 x 64 cols) = sum_seg A_seg(64,K) @ W_seg(cols,K)^T, tf32 mma, fp32 acc.
// grid = NGRP * SPLIT_. 256 threads, 8 warps: warp tile 32(m) x 16(n).
// mode 1: cols {gate*H + n0 + j} (n0=grp*16), LSTM cell epilogue.
// mode 0: cols n0..n0+63 (n0=grp*64), tanh -> hout + rounded -> g_feed.
// mode 2: plain store -> hout.
#define STRD_ 36
#define STGF_ (64*STRD_*2)   // 4608 floats per stage (A 64x36 + W 64x36)
__global__ __launch_bounds__(256) void gemm_kernel(
    const float* __restrict__ A0, int lda0, const float* __restrict__ W0, int ldw0, int kt0,
    const float* __restrict__ A1, int lda1, const float* __restrict__ W1, int ldw1, int kt1,
    const float* __restrict__ A2, int lda2, const float* __restrict__ W2, int ldw2, int kt2,
    int mode,
    const float* __restrict__ bi, const float* __restrict__ bh,
    const float* __restrict__ cprev, float* __restrict__ cout,
    float* __restrict__ hout, float* __restrict__ hraw) {

    extern __shared__ __align__(16) float sm[];   // 4 stages * STGF_

    const int tid = threadIdx.x;
    const int w = tid >> 5, lane = tid & 31;
    const int wm = w >> 2, wn = w & 3;            // 2 x 4 warp grid
    const int g8 = lane >> 2, tg = lane & 3;
    const int grp = blockIdx.x / SPLIT_;
    const int sk  = blockIdx.x % SPLIT_;
    const int n0  = grp * (mode == 1 ? 16 : 64);

    const int tot = kt0 + kt1 + kt2;
    const int cpk = tot / SPLIT_;
    const int cbase = sk * cpk;

    // copy map: 4 x 16B chunks per thread per stage (2 A, 2 W)
    int rA[2], cA[2], rW[2], wrW[2];
#pragma unroll
    for (int j = 0; j < 2; j++) {
        int q = j * 256 + tid;              // 0..511 over A
        rA[j] = q >> 3; cA[j] = (q & 7) * 4;
        rW[j] = rA[j];                      // same pattern for W
        wrW[j] = (mode == 1) ? ((rW[j] >> 4) * H_ + n0 + (rW[j] & 15)) : (n0 + rW[j]);
    }

    auto issue = [&](int c, int buf) {
        const float* Ab; const float* Wb; int la, lw, ko;
        if (c < kt0)            { Ab = A0; Wb = W0; la = lda0; lw = ldw0; ko = c * 32; }
        else if (c < kt0 + kt1) { Ab = A1; Wb = W1; la = lda1; lw = ldw1; ko = (c - kt0) * 32; }
        else                    { Ab = A2; Wb = W2; la = lda2; lw = ldw2; ko = (c - kt0 - kt1) * 32; }
        float* st = sm + buf * STGF_;
#pragma unroll
        for (int j = 0; j < 2; j++)
            cp16(st + rA[j] * STRD_ + cA[j], Ab + (size_t)rA[j] * la + ko + cA[j]);
#pragma unroll
        for (int j = 0; j < 2; j++)
            cp16(st + 64 * STRD_ + rW[j] * STRD_ + cA[j], Wb + (size_t)wrW[j] * lw + ko + cA[j]);
        asm volatile("cp.async.commit_group;\n");
    };

    float acc[2][2][4];
#pragma unroll
    for (int mi = 0; mi < 2; mi++)
#pragma unroll
        for (int ni = 0; ni < 2; ni++)
#pragma unroll
            for (int e = 0; e < 4; e++) acc[mi][ni][e] = 0.f;

    const int npro = cpk < 3 ? cpk : 3;
    for (int s = 0; s < npro; s++) issue(cbase + s, s);

    for (int i = 0; i < cpk; i++) {
        const int rem = cpk - 1 - i;
        if (rem >= 2)      asm volatile("cp.async.wait_group 2;\n");
        else if (rem == 1) asm volatile("cp.async.wait_group 1;\n");
        else               asm volatile("cp.async.wait_group 0;\n");
        __syncthreads();
        if (i + 3 < cpk) issue(cbase + i + 3, (i + 3) & 3);

        const float* stg = sm + (i & 3) * STGF_;
        const uint32_t* pA = (const uint32_t*)stg + (wm * 32 + g8) * STRD_ + tg;
        const uint32_t* pB = (const uint32_t*)(stg + 64 * STRD_) + (wn * 16 + g8) * STRD_ + tg;
#pragma unroll
        for (int s = 0; s < 4; s++) {
            const int ko = s * 8;
            uint32_t a0[4], a1[4], b[2][2];
            a0[0] = pA[ko];                   a0[1] = pA[8 * STRD_ + ko];
            a0[2] = pA[ko + 4];               a0[3] = pA[8 * STRD_ + ko + 4];
            a1[0] = pA[16 * STRD_ + ko];      a1[1] = pA[24 * STRD_ + ko];
            a1[2] = pA[16 * STRD_ + ko + 4];  a1[3] = pA[24 * STRD_ + ko + 4];
            b[0][0] = pB[ko];            b[0][1] = pB[ko + 4];
            b[1][0] = pB[8 * STRD_ + ko]; b[1][1] = pB[8 * STRD_ + ko + 4];
            mma8(acc[0][0], a0, b[0]);
            mma8(acc[0][1], a0, b[1]);
            mma8(acc[1][0], a1, b[0]);
            mma8(acc[1][1], a1, b[1]);
        }
    }

    // write this CTA's 64x64 partial
    {
        float* pp = g_part + (size_t)blockIdx.x * 4096;
#pragma unroll
        for (int mi = 0; mi < 2; mi++)
#pragma unroll
            for (int ni = 0; ni < 2; ni++) {
                int r = wm * 32 + mi * 16 + g8, c = wn * 16 + ni * 8 + tg * 2;
                *(float2*)(pp + r * 64 + c)       = make_float2(acc[mi][ni][0], acc[mi][ni][1]);
                *(float2*)(pp + (r + 8) * 64 + c) = make_float2(acc[mi][ni][2], acc[mi][ni][3]);
            }
    }
    __threadfence();
    __syncthreads();

    __shared__ int isLast;
    if (tid == 0) {
        int old = atomicAdd(&g_cnt[grp], 1);
        isLast = (old == SPLIT_ - 1);
    }
    __syncthreads();
    if (!isLast) return;
    if (tid == 0) g_cnt[grp] = 0;
    __threadfence();

    // deterministic reduction of the SPLIT_ partials into smem
    float* red = sm;
    for (int e = tid; e < 1024; e += 256) {
        const float* p0 = g_part + (size_t)(grp * SPLIT_) * 4096 + e * 4;
        float4 s = *(const float4*)(p0);
#pragma unroll
        for (int p = 1; p < SPLIT_; p++) {
            float4 v = *(const float4*)(p0 + (size_t)p * 4096);
            s.x += v.x; s.y += v.y; s.z += v.z; s.w += v.w;
        }
        *(float4*)(red + e * 4) = s;
    }
    __syncthreads();

    if (mode == 1) {
        for (int e = tid; e < 1024; e += 256) {
            int m = e >> 4, j = e & 15, n = n0 + j;
            float iv = red[m * 64 + j]      + bi[n]           + bh[n];
            float fv = red[m * 64 + 16 + j] + bi[H_ + n]      + bh[H_ + n];
            float gv = red[m * 64 + 32 + j] + bi[2 * H_ + n]  + bh[2 * H_ + n];
            float ov = red[m * 64 + 48 + j] + bi[3 * H_ + n]  + bh[3 * H_ + n];
            float cp = cprev[(size_t)m * H_ + n];
            float c2 = sigf(fv) * cp + sigf(iv) * tanhf(gv);
            float h2 = sigf(ov) * tanhf(c2);
            cout[(size_t)m * H_ + n] = c2;
            hraw[(size_t)m * H_ + n] = h2;
            hout[(size_t)m * H_ + n] = to_tf32(h2);
        }
    } else if (mode == 0) {
        for (int e = tid; e < 4096; e += 256) {
            int m = e >> 6, c = e & 63;
            float v = tanhf(red[e]);
            hout[(size_t)m * H_ + n0 + c]   = v;
            g_feed[(size_t)m * H_ + n0 + c] = to_tf32(v);
        }
    } else {
        for (int e = tid; e < 4096; e += 256) {
            int m = e >> 6, c = e & 63;
            hout[(size_t)m * H_ + n0 + c] = red[e];
        }
    }
}

// ---------------- attention scores: grid (8, B), 256 thr; CTA -> 16 s ----------------
__global__ __launch_bounds__(256) void score_kernel(const float* __restrict__ ctx) {
    __shared__ __align__(16) float qs[H_];
    const int b = blockIdx.y, qd = blockIdx.x, tid = threadIdx.x;
    ((float4*)qs)[tid] = ((const float4*)(g_q + (size_t)b * H_))[tid];
    __syncthreads();
    const int w = tid >> 5, l = tid & 31;
    const float4* q4 = (const float4*)qs;
#pragma unroll
    for (int i = 0; i < 2; i++) {
        const int s = qd * 16 + w * 2 + i;
        const float4* row = (const float4*)(ctx + ((size_t)s * B_ + b) * H_);
        float acc = 0.f;
#pragma unroll
        for (int j = 0; j < 8; j++) {
            float4 a = q4[j * 32 + l], c = row[j * 32 + l];
            acc += a.x * c.x + a.y * c.y + a.z * c.z + a.w * c.w;
        }
#pragma unroll
        for (int o = 16; o > 0; o >>= 1) acc += __shfl_xor_sync(0xFFFFFFFFu, acc, o);
        if (!l) g_scores[b * S_ + s] = acc;
    }
}

// ---------------- softmax + cvec: grid (4, B), 256 thr ----------------
__global__ __launch_bounds__(256) void softcvec_kernel(const float* __restrict__ ctx,
                                                       float* __restrict__ attns_t) {
    __shared__ float sc[S_];
    __shared__ float sal[S_];
    __shared__ float red[8];
    const int b = blockIdx.y, qd = blockIdx.x, tid = threadIdx.x;
    const int w = tid >> 5, l = tid & 31;

    if (tid < 128) sc[tid] = g_scores[b * S_ + tid];
    __syncthreads();

    float mx = -3.4e38f;
    if (tid < 128) mx = sc[tid];
#pragma unroll
    for (int o = 16; o > 0; o >>= 1) mx = fmaxf(mx, __shfl_xor_sync(0xFFFFFFFFu, mx, o));
    if (tid < 128 && !l) red[w] = mx;
    __syncthreads();
    const float gmx = fmaxf(fmaxf(red[0], red[1]), fmaxf(red[2], red[3]));
    float e = 0.f;
    if (tid < 128) { e = expf(sc[tid] - gmx); sal[tid] = e; }
    float se = e;
#pragma unroll
    for (int o = 16; o > 0; o >>= 1) se += __shfl_xor_sync(0xFFFFFFFFu, se, o);
    if (tid < 128 && !l) red[4 + w] = se;
    __syncthreads();
    const float inv = 1.f / (red[4] + red[5] + red[6] + red[7]);
    if (tid < 128) {
        float a = sal[tid] * inv;
        sal[tid] = a;
        if (qd == 0) attns_t[(size_t)b * S_ + tid] = a;
    }
    __syncthreads();

    const int d = qd * 256 + tid;
    float acc = 0.f;
#pragma unroll 16
    for (int s = 0; s < S_; s++) acc += sal[s] * ctx[((size_t)s * B_ + b) * H_ + d];
    g_cvec[(size_t)b * H_ + d] = to_tf32(acc);
}

// ---------------- finalize ----------------
__global__ __launch_bounds__(256) void finalize_kernel(float* __restrict__ hF, float* __restrict__ cF) {
    int i = blockIdx.x * blockDim.x + threadIdx.x;
    if (i < BH_) {
        hF[i]       = g_hraw0[i];
        hF[BH_ + i] = g_hraw1[i];
        cF[i]       = g_cb0[i];
        cF[BH_ + i] = g_cb1[i];
    }
}

// ---------------- host launcher ----------------
extern "C" void kernel_launch(void* const* d_in, const int* in_sizes, int n_in,
                              void* d_out, int out_size) {
    const float* inp   = (const float*)d_in[0];
    const float* ctx   = (const float*)d_in[1];
    const float* h0in  = (const float*)d_in[2];
    const float* c0in  = (const float*)d_in[3];
    const float* W_ih0 = (const float*)d_in[4];
    const float* b_ih0 = (const float*)d_in[5];
    const float* W_hh0 = (const float*)d_in[6];
    const float* b_hh0 = (const float*)d_in[7];
    const float* W_ih1 = (const float*)d_in[8];
    const float* b_ih1 = (const float*)d_in[9];
    const float* W_hh1 = (const float*)d_in[10];
    const float* b_hh1 = (const float*)d_in[11];
    const float* W_a   = (const float*)d_in[12];
    const float* W_out = (const float*)d_in[13];

    float* out   = (float*)d_out;
    float* outs  = out;                 // (T,B,H)
    float* hF    = out + TBH_;          // (2,B,H)
    float* cF    = hF + 2 * BH_;        // (2,B,H)
    float* attns = cF + 2 * BH_;        // (T,B,S)

    float *wih0, *whh0, *wih1, *whh1, *wa, *wout_s;
    float *ginp, *hb0, *hb1, *hraw0, *hraw1, *cb0, *cb1, *q, *cvec, *feed, *zeros;
    cudaGetSymbolAddress((void**)&wih0, g_wih0);
    cudaGetSymbolAddress((void**)&whh0, g_whh0);
    cudaGetSymbolAddress((void**)&wih1, g_wih1);
    cudaGetSymbolAddress((void**)&whh1, g_whh1);
    cudaGetSymbolAddress((void**)&wa, g_wa);
    cudaGetSymbolAddress((void**)&wout_s, g_wout);
    cudaGetSymbolAddress((void**)&ginp, g_inp);
    cudaGetSymbolAddress((void**)&hb0, g_hb0);
    cudaGetSymbolAddress((void**)&hb1, g_hb1);
    cudaGetSymbolAddress((void**)&hraw0, g_hraw0);
    cudaGetSymbolAddress((void**)&hraw1, g_hraw1);
    cudaGetSymbolAddress((void**)&cb0, g_cb0);
    cudaGetSymbolAddress((void**)&cb1, g_cb1);
    cudaGetSymbolAddress((void**)&q, g_q);
    cudaGetSymbolAddress((void**)&cvec, g_cvec);
    cudaGetSymbolAddress((void**)&feed, g_feed);
    cudaGetSymbolAddress((void**)&zeros, g_zeros);

    const int smemB = 4 * STGF_ * sizeof(float);   // 73728
    static int attrSet = 0;
    if (!attrSet) {
        cudaFuncSetAttribute(gemm_kernel, cudaFuncAttributeMaxDynamicSharedMemorySize, smemB);
        attrSet = 1;
    }

    prep_weights<<<2048, 512>>>(W_ih0, W_hh0, W_ih1, W_hh1, W_a, W_out);
    prep_state<<<1024, 512>>>(inp, h0in, c0in);

    for (int t = 0; t < T_; t++) {
        const float* fd  = t ? feed : zeros;
        const float* h0p = hb0 + (size_t)(t & 1) * BH_;
        const float* h1p = hb1 + (size_t)(t & 1) * BH_;
        float* h0n = hb0 + (size_t)((t + 1) & 1) * BH_;
        float* h1n = hb1 + (size_t)((t + 1) & 1) * BH_;

        // layer 0: gates = [emb, feed] @ W_ih0^T + h0 @ W_hh0^T  (64 grp x 8 split)
        gemm_kernel<<<64 * SPLIT_, 256, smemB>>>(
            ginp + (size_t)t * B_ * E_, E_, wih0,       EH_, 16,
            fd,                         H_, wih0 + E_,  EH_, 32,
            h0p,                        H_, whh0,       H_,  32,
            1, b_ih0, b_hh0, cb0, cb0, h0n, hraw0);

        // layer 1
        gemm_kernel<<<64 * SPLIT_, 256, smemB>>>(
            h0n, H_, wih1, H_, 32,
            h1p, H_, whh1, H_, 32,
            h0n, H_, whh1, H_, 0,
            1, b_ih1, b_hh1, cb1, cb1, h1n, hraw1);

        // q = h1 @ W_a^T  (16 grp x 8 split)
        gemm_kernel<<<16 * SPLIT_, 256, smemB>>>(
            h1n, H_, wa, H_, 32,
            h1n, H_, wa, H_, 0,
            h1n, H_, wa, H_, 0,
            2, b_ih0, b_hh0, cb0, cb0, q, hraw0);

        // attention
        score_kernel<<<dim3(8, B_), 256>>>(ctx);
        softcvec_kernel<<<dim3(4, B_), 256>>>(ctx, attns + (size_t)t * B_ * S_);

        // output projection: attn_h = tanh([cvec, h1] @ W_out^T); also writes g_feed
        gemm_kernel<<<16 * SPLIT_, 256, smemB>>>(
            cvec, H_, wout_s,      2 * H_, 32,
            h1n,  H_, wout_s + H_, 2 * H_, 32,
            h1n,  H_, wout_s,      2 * H_, 0,
            0, b_ih0, b_hh0, cb0, cb0, outs + (size_t)t * B_ * H_, hraw0);
    }

    finalize_kernel<<<(BH_ + 255) / 256, 256>>>(hF, cF);
}